// round 2
// baseline (speedup 1.0000x reference)
#include <cuda_runtime.h>
#include <stdint.h>

#define N_NODES 100000
#define D 128
#define LN_EPS 1e-5f

// H = LN(X) @ W^T + b, staged in a device global (no allocations allowed).
__device__ float g_H[(size_t)N_NODES * D];

// ---------------------------------------------------------------------------
// Kernel 1: fused LayerNorm + Linear (X -> g_H)
//   Block: 256 threads, 64 rows per block.
//   Smem: Ws[d][o] (transposed W, pad 4 for 16B-aligned rows) + xn[64][128].
// ---------------------------------------------------------------------------
#define ROWS_PB 64
#define WS_PITCH 132                       // 128 + 4 pad (528B rows, 16B aligned)
#define SMEM_BYTES ((128 * WS_PITCH + ROWS_PB * D) * 4)

__global__ void ln_linear_kernel(const float* __restrict__ X,
                                 const float* __restrict__ gamma,
                                 const float* __restrict__ beta,
                                 const float* __restrict__ W,
                                 const float* __restrict__ bias) {
    extern __shared__ float smem[];
    float* Ws = smem;                      // [128][WS_PITCH]  Ws[d][o] = W[o][d]
    float* xn = smem + 128 * WS_PITCH;     // [ROWS_PB][D]

    const int tid  = threadIdx.x;
    const int lane = tid & 31;
    const int warp = tid >> 5;
    const int row0 = blockIdx.x * ROWS_PB;

    // Load + transpose W into smem.
    for (int i = tid; i < 128 * 128; i += 256) {
        int o = i >> 7;
        int d = i & 127;
        Ws[d * WS_PITCH + o] = W[i];
    }

    // LayerNorm: each of the 8 warps handles 8 rows.
    for (int r = warp; r < ROWS_PB; r += 8) {
        const int row = row0 + r;
        float4 v = make_float4(0.f, 0.f, 0.f, 0.f);
        if (row < N_NODES)
            v = reinterpret_cast<const float4*>(X + (size_t)row * D)[lane];
        float s  = v.x + v.y + v.z + v.w;
        float sq = v.x * v.x + v.y * v.y + v.z * v.z + v.w * v.w;
        #pragma unroll
        for (int off = 16; off; off >>= 1) {
            s  += __shfl_xor_sync(0xffffffffu, s,  off);
            sq += __shfl_xor_sync(0xffffffffu, sq, off);
        }
        const float mu  = s * (1.0f / D);
        const float var = sq * (1.0f / D) - mu * mu;
        const float inv = rsqrtf(var + LN_EPS);
        const float4 g  = reinterpret_cast<const float4*>(gamma)[lane];
        const float4 be = reinterpret_cast<const float4*>(beta)[lane];
        float4 o;
        o.x = (v.x - mu) * inv * g.x + be.x;
        o.y = (v.y - mu) * inv * g.y + be.y;
        o.z = (v.z - mu) * inv * g.z + be.z;
        o.w = (v.w - mu) * inv * g.w + be.w;
        reinterpret_cast<float4*>(xn + r * D)[lane] = o;
    }
    __syncthreads();

    // GEMM: thread (tr,tc) computes 8 rows x 4 cols.
    const int tc = tid & 31;
    const int tr = tid >> 5;
    const float* xs = xn + tr * 8 * D;

    float acc[8][4];
    #pragma unroll
    for (int i = 0; i < 8; ++i)
        acc[i][0] = acc[i][1] = acc[i][2] = acc[i][3] = 0.f;

    #pragma unroll 2
    for (int d = 0; d < D; ++d) {
        const float4 wv =
            *reinterpret_cast<const float4*>(Ws + d * WS_PITCH + (tc << 2));
        #pragma unroll
        for (int i = 0; i < 8; ++i) {
            const float x = xs[i * D + d];
            acc[i][0] = fmaf(x, wv.x, acc[i][0]);
            acc[i][1] = fmaf(x, wv.y, acc[i][1]);
            acc[i][2] = fmaf(x, wv.z, acc[i][2]);
            acc[i][3] = fmaf(x, wv.w, acc[i][3]);
        }
    }

    const float4 bv = reinterpret_cast<const float4*>(bias)[tc];
    #pragma unroll
    for (int i = 0; i < 8; ++i) {
        const int row = row0 + tr * 8 + i;
        if (row < N_NODES) {
            float4 hv;
            hv.x = acc[i][0] + bv.x;
            hv.y = acc[i][1] + bv.y;
            hv.z = acc[i][2] + bv.z;
            hv.w = acc[i][3] + bv.w;
            reinterpret_cast<float4*>(g_H + (size_t)row * D)[tc] = hv;
        }
    }
}

// ---------------------------------------------------------------------------
// Kernel 2: edge scatter  out[dst] += w * H[src]
//   One edge per warp iteration: 1 LDG.128 + 1 RED.v4 per lane.
//   NOTE: edge indices are int32 (JAX x64-disabled downgrades int64 -> int32).
// ---------------------------------------------------------------------------
__global__ void scatter_kernel(const int* __restrict__ esrc,
                               const int* __restrict__ edst,
                               const float* __restrict__ ew,
                               float* __restrict__ out, int E) {
    const int lane    = threadIdx.x & 31;
    const int gw      = (blockIdx.x * blockDim.x + threadIdx.x) >> 5;
    const int nwarps  = (gridDim.x * blockDim.x) >> 5;

    for (int e = gw; e < E; e += nwarps) {
        const int s = esrc[e];             // uniform per warp (L1 broadcast)
        const int d = edst[e];
        const float w = ew[e];
        const float4 hv =
            reinterpret_cast<const float4*>(g_H + (size_t)s * D)[lane];
        float* op = out + (size_t)d * D + (lane << 2);
#if __CUDA_ARCH__ >= 900
        asm volatile("red.global.add.v4.f32 [%0], {%1, %2, %3, %4};"
                     :: "l"(op), "f"(hv.x * w), "f"(hv.y * w),
                        "f"(hv.z * w), "f"(hv.w * w)
                     : "memory");
#else
        atomicAdd(op + 0, hv.x * w);
        atomicAdd(op + 1, hv.y * w);
        atomicAdd(op + 2, hv.z * w);
        atomicAdd(op + 3, hv.w * w);
#endif
    }
}

// ---------------------------------------------------------------------------
// Kernel 3: out = relu(out) + X
// ---------------------------------------------------------------------------
__global__ void finalize_kernel(const float* __restrict__ X,
                                float* __restrict__ out, int n4) {
    const int stride = gridDim.x * blockDim.x;
    for (int i = blockIdx.x * blockDim.x + threadIdx.x; i < n4; i += stride) {
        float4 o = reinterpret_cast<float4*>(out)[i];
        const float4 x = reinterpret_cast<const float4*>(X)[i];
        o.x = fmaxf(o.x, 0.f) + x.x;
        o.y = fmaxf(o.y, 0.f) + x.y;
        o.z = fmaxf(o.z, 0.f) + x.z;
        o.w = fmaxf(o.w, 0.f) + x.w;
        reinterpret_cast<float4*>(out)[i] = o;
    }
}

// ---------------------------------------------------------------------------
extern "C" void kernel_launch(void* const* d_in, const int* in_sizes, int n_in,
                              void* d_out, int out_size) {
    const float* X        = (const float*)d_in[0];
    const int*   esrc     = (const int*)d_in[1];
    const int*   edst     = (const int*)d_in[2];
    const float* ew       = (const float*)d_in[3];
    const float* gamma    = (const float*)d_in[4];
    const float* beta     = (const float*)d_in[5];
    const float* W        = (const float*)d_in[6];
    const float* bias     = (const float*)d_in[7];
    float* out            = (float*)d_out;
    const int E           = in_sizes[1];

    cudaFuncSetAttribute(ln_linear_kernel,
                         cudaFuncAttributeMaxDynamicSharedMemorySize,
                         SMEM_BYTES);

    // out accumulates the SpMM — zero it first (d_out is poisoned).
    cudaMemsetAsync(d_out, 0, (size_t)out_size * sizeof(float));

    const int grid1 = (N_NODES + ROWS_PB - 1) / ROWS_PB;
    ln_linear_kernel<<<grid1, 256, SMEM_BYTES>>>(X, gamma, beta, W, bias);

    scatter_kernel<<<2048, 256>>>(esrc, edst, ew, out, E);

    const int n4 = (N_NODES * D) / 4;
    finalize_kernel<<<1024, 256>>>(X, out, n4);
}

// round 4
// speedup vs baseline: 1.4619x; 1.4619x over previous
#include <cuda_runtime.h>
#include <stdint.h>

#define N_NODES 100000
#define N_EDGES 3200000
#define D 128
#define LN_EPS 1e-5f

// ---------------------------------------------------------------------------
// Device-global scratch (no allocations allowed).
// ---------------------------------------------------------------------------
__device__ float g_H[(size_t)N_NODES * D];     // LN(X) @ W^T + b
__device__ int   g_off[N_NODES + 1];           // CSR offsets (by dst)
__device__ int   g_cur[N_NODES];               // bucket cursors
__device__ int2  g_sw[N_EDGES];                // packed (src, w_bits) sorted by dst
__device__ int   g_bsum[128];                  // scan block sums

// ===========================================================================
// Kernel 1: fused LayerNorm + Linear (X -> g_H), f32x2 packed FMA.
//   ROWS_PB=32 rows/block, 256 threads, 2 blocks/SM.
//   Smem: Ws[d][o] transposed W (pitch 132) + xn2 = splatted {x,x} pairs.
// ===========================================================================
#define ROWS_PB 32
#define WS_PITCH 132
#define XN2_OFF (128 * WS_PITCH)                       // in floats
#define SMEM_BYTES ((128 * WS_PITCH) * 4 + ROWS_PB * D * 8)

__global__ void __launch_bounds__(256, 2)
ln_linear_kernel(const float* __restrict__ X,
                 const float* __restrict__ gamma,
                 const float* __restrict__ beta,
                 const float* __restrict__ W,
                 const float* __restrict__ bias) {
    extern __shared__ float smem[];
    float*  Ws  = smem;                                // [128][132], Ws[d][o]=W[o][d]
    float2* xn2 = reinterpret_cast<float2*>(smem + XN2_OFF);  // [ROWS_PB*D] splats

    const int tid  = threadIdx.x;
    const int lane = tid & 31;
    const int warp = tid >> 5;
    const int row0 = blockIdx.x * ROWS_PB;

    // Load + transpose W into smem.
    for (int i = tid; i < 128 * 128; i += 256) {
        int o = i >> 7;
        int d = i & 127;
        Ws[d * WS_PITCH + o] = W[i];
    }

    // LayerNorm: 8 warps x 4 rows each; write splatted pairs {h,h}.
    #pragma unroll
    for (int rr = 0; rr < ROWS_PB / 8; ++rr) {
        const int r   = warp + rr * 8;
        const int row = row0 + r;                      // grid exactly covers N
        const float4 v = reinterpret_cast<const float4*>(X + (size_t)row * D)[lane];
        float s  = v.x + v.y + v.z + v.w;
        float sq = v.x * v.x + v.y * v.y + v.z * v.z + v.w * v.w;
        #pragma unroll
        for (int off = 16; off; off >>= 1) {
            s  += __shfl_xor_sync(0xffffffffu, s,  off);
            sq += __shfl_xor_sync(0xffffffffu, sq, off);
        }
        const float mu  = s * (1.0f / D);
        const float var = sq * (1.0f / D) - mu * mu;
        const float inv = rsqrtf(var + LN_EPS);
        const float4 g  = reinterpret_cast<const float4*>(gamma)[lane];
        const float4 be = reinterpret_cast<const float4*>(beta)[lane];
        float h0 = (v.x - mu) * inv * g.x + be.x;
        float h1 = (v.y - mu) * inv * g.y + be.y;
        float h2 = (v.z - mu) * inv * g.z + be.z;
        float h3 = (v.w - mu) * inv * g.w + be.w;
        float2* xp = xn2 + r * D + lane * 4;
        xp[0] = make_float2(h0, h0);
        xp[1] = make_float2(h1, h1);
        xp[2] = make_float2(h2, h2);
        xp[3] = make_float2(h3, h3);
    }
    __syncthreads();

    // GEMM: thread (tr, tc): rows tr*4..+3, cols tc*4..+3.
    const int tc = tid & 31;
    const int tr = tid >> 5;

    unsigned long long acc01[4], acc23[4];
    #pragma unroll
    for (int i = 0; i < 4; ++i) { acc01[i] = 0ull; acc23[i] = 0ull; }

    const unsigned long long* xbase =
        reinterpret_cast<const unsigned long long*>(xn2) + tr * 4 * D;
    const float* wbase = Ws + (tc << 2);

    #pragma unroll 4
    for (int d = 0; d < D; ++d) {
        const ulonglong2 wv =
            *reinterpret_cast<const ulonglong2*>(wbase + d * WS_PITCH);
        #pragma unroll
        for (int r = 0; r < 4; ++r) {
            const unsigned long long xs = xbase[r * D + d];   // {x,x}
            asm("fma.rn.f32x2 %0, %1, %2, %0;" : "+l"(acc01[r]) : "l"(xs), "l"(wv.x));
            asm("fma.rn.f32x2 %0, %1, %2, %0;" : "+l"(acc23[r]) : "l"(xs), "l"(wv.y));
        }
    }

    const float4 bv = reinterpret_cast<const float4*>(bias)[tc];
    #pragma unroll
    for (int r = 0; r < 4; ++r) {
        const int row = row0 + tr * 4 + r;
        float4 hv;
        hv.x = __uint_as_float((unsigned)(acc01[r] & 0xffffffffull)) + bv.x;
        hv.y = __uint_as_float((unsigned)(acc01[r] >> 32))           + bv.y;
        hv.z = __uint_as_float((unsigned)(acc23[r] & 0xffffffffull)) + bv.z;
        hv.w = __uint_as_float((unsigned)(acc23[r] >> 32))           + bv.w;
        reinterpret_cast<float4*>(g_H + (size_t)row * D)[tc] = hv;
    }
}

// ===========================================================================
// CSR build: histogram -> scan -> reorder
// ===========================================================================
__global__ void hist_kernel(const int* __restrict__ edst, int E) {
    const int stride = gridDim.x * blockDim.x;
    for (int e = blockIdx.x * blockDim.x + threadIdx.x; e < E; e += stride)
        atomicAdd(&g_off[edst[e] + 1], 1);
}

__device__ __forceinline__ int warp_incl_scan(int v, int lane) {
    #pragma unroll
    for (int off = 1; off < 32; off <<= 1) {
        int t = __shfl_up_sync(0xffffffffu, v, off);
        if (lane >= off) v += t;
    }
    return v;
}

__global__ void scan_chunk_kernel(int n) {        // blockDim = 1024
    __shared__ int wsum[32];
    const int tid  = threadIdx.x;
    const int lane = tid & 31;
    const int wid  = tid >> 5;
    const int gi   = blockIdx.x * 1024 + tid;
    int v = (gi < n) ? g_off[gi] : 0;
    v = warp_incl_scan(v, lane);
    if (lane == 31) wsum[wid] = v;
    __syncthreads();
    if (wid == 0) wsum[lane] = warp_incl_scan(wsum[lane], lane);
    __syncthreads();
    if (wid > 0) v += wsum[wid - 1];
    if (gi < n) g_off[gi] = v;
    if (tid == 1023) g_bsum[blockIdx.x] = v;
}

__global__ void scan_bsum_kernel(int nb) {        // 1 block, 128 threads
    __shared__ int wsum[4];
    const int tid  = threadIdx.x;
    const int lane = tid & 31;
    const int wid  = tid >> 5;
    int v = (tid < nb) ? g_bsum[tid] : 0;
    v = warp_incl_scan(v, lane);
    if (lane == 31) wsum[wid] = v;
    __syncthreads();
    int add = 0;
    #pragma unroll
    for (int w = 0; w < 4; ++w) add += (w < wid) ? wsum[w] : 0;
    if (tid < nb) g_bsum[tid] = v + add;
}

__global__ void scan_add_kernel(int n) {          // blockDim = 1024
    const int gi = blockIdx.x * 1024 + threadIdx.x;
    if (gi >= n) return;
    const int add = (blockIdx.x > 0) ? g_bsum[blockIdx.x - 1] : 0;
    const int val = g_off[gi] + add;
    g_off[gi] = val;
    if (gi < N_NODES) g_cur[gi] = val;
}

__global__ void reorder_kernel(const int* __restrict__ esrc,
                               const int* __restrict__ edst,
                               const float* __restrict__ ew, int E) {
    const int stride = gridDim.x * blockDim.x;
    for (int e = blockIdx.x * blockDim.x + threadIdx.x; e < E; e += stride) {
        const int dst = edst[e];
        const int pos = atomicAdd(&g_cur[dst], 1);
        g_sw[pos] = make_int2(esrc[e], __float_as_int(ew[e]));
    }
}

// ===========================================================================
// Aggregate: one warp per dst node. out = relu(sum w*H[src]) + X.
// ===========================================================================
__global__ void __launch_bounds__(256)
aggregate_kernel(const float* __restrict__ X, float* __restrict__ out) {
    const int gw = (blockIdx.x * blockDim.x + threadIdx.x) >> 5;
    if (gw >= N_NODES) return;
    const int lane = threadIdx.x & 31;

    const int beg = g_off[gw];
    const int end = g_off[gw + 1];

    float4 acc = make_float4(0.f, 0.f, 0.f, 0.f);
    int e = beg;
    for (; e + 1 < end; e += 2) {                 // unroll-2 for gather MLP
        const int2 sw0 = __ldcs(&g_sw[e]);
        const int2 sw1 = __ldcs(&g_sw[e + 1]);
        const float4 h0 = __ldg(
            reinterpret_cast<const float4*>(g_H + (size_t)sw0.x * D) + lane);
        const float4 h1 = __ldg(
            reinterpret_cast<const float4*>(g_H + (size_t)sw1.x * D) + lane);
        const float w0 = __int_as_float(sw0.y);
        const float w1 = __int_as_float(sw1.y);
        acc.x = fmaf(w0, h0.x, acc.x); acc.y = fmaf(w0, h0.y, acc.y);
        acc.z = fmaf(w0, h0.z, acc.z); acc.w = fmaf(w0, h0.w, acc.w);
        acc.x = fmaf(w1, h1.x, acc.x); acc.y = fmaf(w1, h1.y, acc.y);
        acc.z = fmaf(w1, h1.z, acc.z); acc.w = fmaf(w1, h1.w, acc.w);
    }
    if (e < end) {
        const int2 sw = __ldcs(&g_sw[e]);
        const float4 h = __ldg(
            reinterpret_cast<const float4*>(g_H + (size_t)sw.x * D) + lane);
        const float w = __int_as_float(sw.y);
        acc.x = fmaf(w, h.x, acc.x); acc.y = fmaf(w, h.y, acc.y);
        acc.z = fmaf(w, h.z, acc.z); acc.w = fmaf(w, h.w, acc.w);
    }

    const float4 xv =
        __ldcs(reinterpret_cast<const float4*>(X + (size_t)gw * D) + lane);
    float4 o;
    o.x = fmaxf(acc.x, 0.f) + xv.x;
    o.y = fmaxf(acc.y, 0.f) + xv.y;
    o.z = fmaxf(acc.z, 0.f) + xv.z;
    o.w = fmaxf(acc.w, 0.f) + xv.w;
    __stcs(reinterpret_cast<float4*>(out + (size_t)gw * D) + lane, o);
}

// ===========================================================================
extern "C" void kernel_launch(void* const* d_in, const int* in_sizes, int n_in,
                              void* d_out, int out_size) {
    const float* X     = (const float*)d_in[0];
    const int*   esrc  = (const int*)d_in[1];
    const int*   edst  = (const int*)d_in[2];
    const float* ew    = (const float*)d_in[3];
    const float* gamma = (const float*)d_in[4];
    const float* beta  = (const float*)d_in[5];
    const float* W     = (const float*)d_in[6];
    const float* bias  = (const float*)d_in[7];
    float* out         = (float*)d_out;
    const int E        = in_sizes[1];

    cudaFuncSetAttribute(ln_linear_kernel,
                         cudaFuncAttributeMaxDynamicSharedMemorySize,
                         SMEM_BYTES);

    void* off_ptr = nullptr;
    cudaGetSymbolAddress(&off_ptr, g_off);
    cudaMemsetAsync(off_ptr, 0, (N_NODES + 1) * sizeof(int));

    const int n  = N_NODES + 1;
    const int nb = (n + 1023) / 1024;                 // 98

    hist_kernel<<<1024, 256>>>(edst, E);
    scan_chunk_kernel<<<nb, 1024>>>(n);
    scan_bsum_kernel<<<1, 128>>>(nb);
    scan_add_kernel<<<nb, 1024>>>(n);
    reorder_kernel<<<1024, 256>>>(esrc, edst, ew, E);

    ln_linear_kernel<<<N_NODES / ROWS_PB, 256, SMEM_BYTES>>>(X, gamma, beta, W, bias);

    aggregate_kernel<<<(N_NODES * 32 + 255) / 256, 256>>>(X, out);
}

// round 5
// speedup vs baseline: 1.7113x; 1.1706x over previous
#include <cuda_runtime.h>
#include <cuda_fp16.h>
#include <stdint.h>

#define N_NODES 100000
#define N_EDGES 3200000
#define D 128
#define LN_EPS 1e-5f

// ---------------------------------------------------------------------------
// Device-global scratch (no allocations allowed).
// ---------------------------------------------------------------------------
__device__ __half g_Hh[(size_t)N_NODES * D];   // LN(X) @ W^T + b, fp16
__device__ int   g_off[N_NODES + 1];           // CSR offsets (by dst)
__device__ int   g_cur[N_NODES];               // bucket cursors
__device__ int2  g_sw[N_EDGES];                // packed (src, w_bits) sorted by dst
__device__ int   g_bsum[128];                  // scan block sums

// ===========================================================================
// Kernel 1: fused [LayerNorm + Linear -> g_Hh (fp16)]  +  [edge histogram].
//   Blocks [0, LN_BLOCKS): GEMM role. Blocks [LN_BLOCKS, +HIST_BLOCKS): hist.
// ===========================================================================
#define ROWS_PB 32
#define LN_BLOCKS (N_NODES / ROWS_PB)              // 3125
#define HIST_BLOCKS 1024
#define WS_PITCH 132
#define XN2_OFF (128 * WS_PITCH)                   // in floats
#define SMEM_BYTES ((128 * WS_PITCH) * 4 + ROWS_PB * D * 8)

__global__ void __launch_bounds__(256, 2)
ln_linear_hist_kernel(const float* __restrict__ X,
                      const float* __restrict__ gamma,
                      const float* __restrict__ beta,
                      const float* __restrict__ W,
                      const float* __restrict__ bias,
                      const int* __restrict__ edst, int E) {
    const int tid = threadIdx.x;

    // ---- histogram role -------------------------------------------------
    if (blockIdx.x >= LN_BLOCKS) {
        const int hb     = blockIdx.x - LN_BLOCKS;
        const int stride = HIST_BLOCKS * 256;
        for (int e = hb * 256 + tid; e < E; e += stride)
            atomicAdd(&g_off[__ldcs(&edst[e]) + 1], 1);
        return;
    }

    // ---- LN + GEMM role -------------------------------------------------
    extern __shared__ float smem[];
    float*  Ws  = smem;                                       // [128][132]
    float2* xn2 = reinterpret_cast<float2*>(smem + XN2_OFF);  // splatted {x,x}

    const int lane = tid & 31;
    const int warp = tid >> 5;
    const int row0 = blockIdx.x * ROWS_PB;

    // Load + transpose W into smem.
    for (int i = tid; i < 128 * 128; i += 256) {
        int o = i >> 7;
        int d = i & 127;
        Ws[d * WS_PITCH + o] = W[i];
    }

    // LayerNorm: 8 warps x 4 rows each; write splatted pairs {h,h}.
    #pragma unroll
    for (int rr = 0; rr < ROWS_PB / 8; ++rr) {
        const int r   = warp + rr * 8;
        const int row = row0 + r;
        const float4 v = reinterpret_cast<const float4*>(X + (size_t)row * D)[lane];
        float s  = v.x + v.y + v.z + v.w;
        float sq = v.x * v.x + v.y * v.y + v.z * v.z + v.w * v.w;
        #pragma unroll
        for (int off = 16; off; off >>= 1) {
            s  += __shfl_xor_sync(0xffffffffu, s,  off);
            sq += __shfl_xor_sync(0xffffffffu, sq, off);
        }
        const float mu  = s * (1.0f / D);
        const float var = sq * (1.0f / D) - mu * mu;
        const float inv = rsqrtf(var + LN_EPS);
        const float4 g  = reinterpret_cast<const float4*>(gamma)[lane];
        const float4 be = reinterpret_cast<const float4*>(beta)[lane];
        float h0 = (v.x - mu) * inv * g.x + be.x;
        float h1 = (v.y - mu) * inv * g.y + be.y;
        float h2 = (v.z - mu) * inv * g.z + be.z;
        float h3 = (v.w - mu) * inv * g.w + be.w;
        float2* xp = xn2 + r * D + lane * 4;
        xp[0] = make_float2(h0, h0);
        xp[1] = make_float2(h1, h1);
        xp[2] = make_float2(h2, h2);
        xp[3] = make_float2(h3, h3);
    }
    __syncthreads();

    // GEMM: thread (tr, tc): rows tr*4..+3, cols tc*4..+3. f32x2 packed FMA.
    const int tc = tid & 31;
    const int tr = tid >> 5;

    unsigned long long acc01[4], acc23[4];
    #pragma unroll
    for (int i = 0; i < 4; ++i) { acc01[i] = 0ull; acc23[i] = 0ull; }

    const unsigned long long* xbase =
        reinterpret_cast<const unsigned long long*>(xn2) + tr * 4 * D;
    const float* wbase = Ws + (tc << 2);

    #pragma unroll 4
    for (int d = 0; d < D; ++d) {
        const ulonglong2 wv =
            *reinterpret_cast<const ulonglong2*>(wbase + d * WS_PITCH);
        #pragma unroll
        for (int r = 0; r < 4; ++r) {
            const unsigned long long xs = xbase[r * D + d];   // {x,x}
            asm("fma.rn.f32x2 %0, %1, %2, %0;" : "+l"(acc01[r]) : "l"(xs), "l"(wv.x));
            asm("fma.rn.f32x2 %0, %1, %2, %0;" : "+l"(acc23[r]) : "l"(xs), "l"(wv.y));
        }
    }

    const float4 bv = reinterpret_cast<const float4*>(bias)[tc];
    #pragma unroll
    for (int r = 0; r < 4; ++r) {
        const int row = row0 + tr * 4 + r;
        const float hx = __uint_as_float((unsigned)(acc01[r] & 0xffffffffull)) + bv.x;
        const float hy = __uint_as_float((unsigned)(acc01[r] >> 32))           + bv.y;
        const float hz = __uint_as_float((unsigned)(acc23[r] & 0xffffffffull)) + bv.z;
        const float hw = __uint_as_float((unsigned)(acc23[r] >> 32))           + bv.w;
        const __half2 p01 = __floats2half2_rn(hx, hy);
        const __half2 p23 = __floats2half2_rn(hz, hw);
        uint2 st;
        st.x = *reinterpret_cast<const unsigned*>(&p01);
        st.y = *reinterpret_cast<const unsigned*>(&p23);
        reinterpret_cast<uint2*>(g_Hh + (size_t)row * D)[tc] = st;
    }
}

// ===========================================================================
// CSR build: scan + reorder (histogram fused above)
// ===========================================================================
__device__ __forceinline__ int warp_incl_scan(int v, int lane) {
    #pragma unroll
    for (int off = 1; off < 32; off <<= 1) {
        int t = __shfl_up_sync(0xffffffffu, v, off);
        if (lane >= off) v += t;
    }
    return v;
}

__global__ void scan_chunk_kernel(int n) {        // blockDim = 1024
    __shared__ int wsum[32];
    const int tid  = threadIdx.x;
    const int lane = tid & 31;
    const int wid  = tid >> 5;
    const int gi   = blockIdx.x * 1024 + tid;
    int v = (gi < n) ? g_off[gi] : 0;
    v = warp_incl_scan(v, lane);
    if (lane == 31) wsum[wid] = v;
    __syncthreads();
    if (wid == 0) wsum[lane] = warp_incl_scan(wsum[lane], lane);
    __syncthreads();
    if (wid > 0) v += wsum[wid - 1];
    if (gi < n) g_off[gi] = v;
    if (tid == 1023) g_bsum[blockIdx.x] = v;
}

__global__ void scan_bsum_kernel(int nb) {        // 1 block, 128 threads
    __shared__ int wsum[4];
    const int tid  = threadIdx.x;
    const int lane = tid & 31;
    const int wid  = tid >> 5;
    int v = (tid < nb) ? g_bsum[tid] : 0;
    v = warp_incl_scan(v, lane);
    if (lane == 31) wsum[wid] = v;
    __syncthreads();
    int add = 0;
    #pragma unroll
    for (int w = 0; w < 4; ++w) add += (w < wid) ? wsum[w] : 0;
    if (tid < nb) g_bsum[tid] = v + add;
}

__global__ void scan_add_kernel(int n) {          // blockDim = 1024
    const int gi = blockIdx.x * 1024 + threadIdx.x;
    if (gi >= n) return;
    const int add = (blockIdx.x > 0) ? g_bsum[blockIdx.x - 1] : 0;
    const int val = g_off[gi] + add;
    g_off[gi] = val;
    if (gi < N_NODES) g_cur[gi] = val;
}

__global__ void reorder_kernel(const int* __restrict__ esrc,
                               const int* __restrict__ edst,
                               const float* __restrict__ ew, int E) {
    const int stride = gridDim.x * blockDim.x;
    for (int e = blockIdx.x * blockDim.x + threadIdx.x; e < E; e += stride) {
        const int dst = __ldcs(&edst[e]);
        const int pos = atomicAdd(&g_cur[dst], 1);
        g_sw[pos] = make_int2(__ldcs(&esrc[e]), __float_as_int(__ldcs(&ew[e])));
    }
}

// ===========================================================================
// Aggregate: one warp per dst node. out = relu(sum w*H[src]) + X.
//   fp16 gather (8B/lane), fp32 accumulate.
// ===========================================================================
__device__ __forceinline__ float4 h4_to_f4(uint2 raw) {
    const __half2 a = *reinterpret_cast<const __half2*>(&raw.x);
    const __half2 b = *reinterpret_cast<const __half2*>(&raw.y);
    const float2 f01 = __half22float2(a);
    const float2 f23 = __half22float2(b);
    return make_float4(f01.x, f01.y, f23.x, f23.y);
}

__global__ void __launch_bounds__(256)
aggregate_kernel(const float* __restrict__ X, float* __restrict__ out) {
    const int gw = (blockIdx.x * blockDim.x + threadIdx.x) >> 5;
    if (gw >= N_NODES) return;
    const int lane = threadIdx.x & 31;

    const int beg = g_off[gw];
    const int end = g_off[gw + 1];

    float4 acc = make_float4(0.f, 0.f, 0.f, 0.f);
    int e = beg;
    for (; e + 1 < end; e += 2) {                 // unroll-2 for gather MLP
        const int2 sw0 = __ldcs(&g_sw[e]);
        const int2 sw1 = __ldcs(&g_sw[e + 1]);
        const uint2 r0 = __ldg(
            reinterpret_cast<const uint2*>(g_Hh + (size_t)sw0.x * D) + lane);
        const uint2 r1 = __ldg(
            reinterpret_cast<const uint2*>(g_Hh + (size_t)sw1.x * D) + lane);
        const float4 h0 = h4_to_f4(r0);
        const float4 h1 = h4_to_f4(r1);
        const float w0 = __int_as_float(sw0.y);
        const float w1 = __int_as_float(sw1.y);
        acc.x = fmaf(w0, h0.x, acc.x); acc.y = fmaf(w0, h0.y, acc.y);
        acc.z = fmaf(w0, h0.z, acc.z); acc.w = fmaf(w0, h0.w, acc.w);
        acc.x = fmaf(w1, h1.x, acc.x); acc.y = fmaf(w1, h1.y, acc.y);
        acc.z = fmaf(w1, h1.z, acc.z); acc.w = fmaf(w1, h1.w, acc.w);
    }
    if (e < end) {
        const int2 sw = __ldcs(&g_sw[e]);
        const uint2 r = __ldg(
            reinterpret_cast<const uint2*>(g_Hh + (size_t)sw.x * D) + lane);
        const float4 h = h4_to_f4(r);
        const float w = __int_as_float(sw.y);
        acc.x = fmaf(w, h.x, acc.x); acc.y = fmaf(w, h.y, acc.y);
        acc.z = fmaf(w, h.z, acc.z); acc.w = fmaf(w, h.w, acc.w);
    }

    const float4 xv =
        __ldcs(reinterpret_cast<const float4*>(X + (size_t)gw * D) + lane);
    float4 o;
    o.x = fmaxf(acc.x, 0.f) + xv.x;
    o.y = fmaxf(acc.y, 0.f) + xv.y;
    o.z = fmaxf(acc.z, 0.f) + xv.z;
    o.w = fmaxf(acc.w, 0.f) + xv.w;
    __stcs(reinterpret_cast<float4*>(out + (size_t)gw * D) + lane, o);
}

// ===========================================================================
extern "C" void kernel_launch(void* const* d_in, const int* in_sizes, int n_in,
                              void* d_out, int out_size) {
    const float* X     = (const float*)d_in[0];
    const int*   esrc  = (const int*)d_in[1];
    const int*   edst  = (const int*)d_in[2];
    const float* ew    = (const float*)d_in[3];
    const float* gamma = (const float*)d_in[4];
    const float* beta  = (const float*)d_in[5];
    const float* W     = (const float*)d_in[6];
    const float* bias  = (const float*)d_in[7];
    float* out         = (float*)d_out;
    const int E        = in_sizes[1];

    cudaFuncSetAttribute(ln_linear_hist_kernel,
                         cudaFuncAttributeMaxDynamicSharedMemorySize,
                         SMEM_BYTES);

    void* off_ptr = nullptr;
    cudaGetSymbolAddress(&off_ptr, g_off);
    cudaMemsetAsync(off_ptr, 0, (N_NODES + 1) * sizeof(int));

    const int n  = N_NODES + 1;
    const int nb = (n + 1023) / 1024;                 // 98

    // Fused GEMM + histogram (independent work, one launch).
    ln_linear_hist_kernel<<<LN_BLOCKS + HIST_BLOCKS, 256, SMEM_BYTES>>>(
        X, gamma, beta, W, bias, edst, E);

    scan_chunk_kernel<<<nb, 1024>>>(n);
    scan_bsum_kernel<<<1, 128>>>(nb);
    scan_add_kernel<<<nb, 1024>>>(n);
    reorder_kernel<<<1024, 256>>>(esrc, edst, ew, E);

    aggregate_kernel<<<(N_NODES * 32 + 255) / 256, 256>>>(X, out);
}